// round 3
// baseline (speedup 1.0000x reference)
#include <cuda_runtime.h>
#include <stdint.h>

// PatchMasker: out = concat(where(mask[t], 0, x_dist),
//                           where(mask[t], 0, x_tre),
//                           where(mask[t], 0, x_sea))
// x_* = (B=256, T=512, F=256) fp32, mask = (T=512,) int32.
// HBM-streaming. Masked rows skip input reads (predicated LDG).
// R2 -> R3: 2 float4 per tensor per thread (front-batched -> 6 outstanding
// LDG.128 per thread), streaming cache hints (.cs) since data has no reuse.

#define B_DIM 256
#define T_DIM 512
#define F_DIM 256

#define N4_PER   ((long)B_DIM * T_DIM * F_DIM / 4)   // float4 per tensor
#define NP_PER   (N4_PER / 2)                        // float4-PAIRS per tensor
// 32 pairs per (b,t) row (64 float4 / row): t = (p >> 5) & (T-1)
#define PAIR_ROW_SHIFT 5
#define T_MASK (T_DIM - 1)

__global__ void __launch_bounds__(256, 8)
patch_masker_kernel(const float4* __restrict__ xd,
                    const float4* __restrict__ xt,
                    const float4* __restrict__ xs,
                    const int* __restrict__ mask,
                    float4* __restrict__ out)
{
    long p = (long)blockIdx.x * blockDim.x + threadIdx.x;
    if (p >= NP_PER) return;

    int t = (int)((p >> PAIR_ROW_SHIFT) & T_MASK);
    bool keep = (mask[t] == 0);       // 2 KB table, L1-resident

    long i = p * 2;                   // first float4 of this thread's pair

    const float4 z = make_float4(0.f, 0.f, 0.f, 0.f);
    float4 a0 = z, a1 = z, b0 = z, b1 = z, c0 = z, c1 = z;

    if (keep) {
        // Front-batched independent loads: 6 LDG.128 in flight per thread.
        a0 = __ldcs(&xd[i]);
        a1 = __ldcs(&xd[i + 1]);
        b0 = __ldcs(&xt[i]);
        b1 = __ldcs(&xt[i + 1]);
        c0 = __ldcs(&xs[i]);
        c1 = __ldcs(&xs[i + 1]);
    }

    __stcs(&out[i],                  a0);
    __stcs(&out[i + 1],              a1);
    __stcs(&out[i +     N4_PER],     b0);
    __stcs(&out[i +     N4_PER + 1], b1);
    __stcs(&out[i + 2 * N4_PER],     c0);
    __stcs(&out[i + 2 * N4_PER + 1], c1);
}

extern "C" void kernel_launch(void* const* d_in, const int* in_sizes, int n_in,
                              void* d_out, int out_size)
{
    const float4* xd = (const float4*)d_in[0];
    const float4* xt = (const float4*)d_in[1];
    const float4* xs = (const float4*)d_in[2];
    const int* mask  = (const int*)d_in[3];
    float4* out = (float4*)d_out;

    const int threads = 256;
    const long blocks = (NP_PER + threads - 1) / threads;  // 16384

    patch_masker_kernel<<<(unsigned)blocks, threads>>>(xd, xt, xs, mask, out);
}

// round 4
// speedup vs baseline: 1.1184x; 1.1184x over previous
#include <cuda_runtime.h>
#include <stdint.h>

// PatchMasker: out = concat(where(mask[t], 0, x_dist),
//                           where(mask[t], 0, x_tre),
//                           where(mask[t], 0, x_sea))
// x_* = (B=256, T=512, F=256) fp32, mask = (T=512,) int32.
// HBM-streaming. Masked rows skip input reads (predicated LDG).
// R3 -> R4: fix coalescing. Each block owns 512 consecutive float4 per
// tensor; thread handles [base+tid] and [base+256+tid] (warp-contiguous,
// fully coalesced), giving 6 outstanding LDG.128 per thread without the
// strided-access penalty that sank R3. Streaming (.cs) hints retained.

#define B_DIM 256
#define T_DIM 512
#define F_DIM 256

#define N4_PER ((long)B_DIM * T_DIM * F_DIM / 4)  // float4 per tensor
#define ROW_SHIFT 6                               // 64 float4 per (b,t) row
#define T_MASK (T_DIM - 1)
#define BLK 256
#define F4_PER_BLOCK (2 * BLK)                    // 512 float4 per block

__global__ void __launch_bounds__(BLK, 8)
patch_masker_kernel(const float4* __restrict__ xd,
                    const float4* __restrict__ xt,
                    const float4* __restrict__ xs,
                    const int* __restrict__ mask,
                    float4* __restrict__ out)
{
    long base = (long)blockIdx.x * F4_PER_BLOCK;
    long i0 = base + threadIdx.x;        // coalesced across warp
    long i1 = i0 + BLK;                  // coalesced across warp

    int t0 = (int)((i0 >> ROW_SHIFT) & T_MASK);
    int t1 = (int)((i1 >> ROW_SHIFT) & T_MASK);
    bool k0 = (mask[t0] == 0);           // 2 KB table, L1-resident
    bool k1 = (mask[t1] == 0);

    const float4 z = make_float4(0.f, 0.f, 0.f, 0.f);
    float4 a0 = z, a1 = z, b0 = z, b1 = z, c0 = z, c1 = z;

    // Front-batched independent predicated loads: up to 6 LDG.128 in flight.
    if (k0) {
        a0 = __ldcs(&xd[i0]);
        b0 = __ldcs(&xt[i0]);
        c0 = __ldcs(&xs[i0]);
    }
    if (k1) {
        a1 = __ldcs(&xd[i1]);
        b1 = __ldcs(&xt[i1]);
        c1 = __ldcs(&xs[i1]);
    }

    __stcs(&out[i0],              a0);
    __stcs(&out[i1],              a1);
    __stcs(&out[i0 +     N4_PER], b0);
    __stcs(&out[i1 +     N4_PER], b1);
    __stcs(&out[i0 + 2 * N4_PER], c0);
    __stcs(&out[i1 + 2 * N4_PER], c1);
}

extern "C" void kernel_launch(void* const* d_in, const int* in_sizes, int n_in,
                              void* d_out, int out_size)
{
    const float4* xd = (const float4*)d_in[0];
    const float4* xt = (const float4*)d_in[1];
    const float4* xs = (const float4*)d_in[2];
    const int* mask  = (const int*)d_in[3];
    float4* out = (float4*)d_out;

    const long blocks = N4_PER / F4_PER_BLOCK;   // 16384, exact
    patch_masker_kernel<<<(unsigned)blocks, BLK>>>(xd, xt, xs, mask, out);
}

// round 5
// speedup vs baseline: 1.1188x; 1.0003x over previous
#include <cuda_runtime.h>
#include <stdint.h>

// PatchMasker: out = concat(where(mask[t], 0, x_dist),
//                           where(mask[t], 0, x_tre),
//                           where(mask[t], 0, x_sea))
// x_* = (B=256, T=512, F=256) fp32, mask = (T=512,) int32.
// HBM-streaming; masked rows skip the input read (predicated LDG).
//
// R4 -> R5: one tensor per blockIdx.y so each block drives exactly one read
// stream + one write stream (vs 6 interleaved streams in R4), improving DRAM
// page locality / reducing R-W turnaround. 4 coalesced float4 per thread.

#define B_DIM 256
#define T_DIM 512
#define F_DIM 256

#define N4_PER ((long)B_DIM * T_DIM * F_DIM / 4)  // float4 per tensor = 8388608
#define ROW_SHIFT 6                               // 64 float4 per (b,t) row
#define T_MASK (T_DIM - 1)
#define BLK 256
#define F4_PER_THREAD 4
#define F4_PER_BLOCK (F4_PER_THREAD * BLK)        // 1024

__global__ void __launch_bounds__(BLK, 8)
patch_masker_kernel(const float4* __restrict__ xd,
                    const float4* __restrict__ xt,
                    const float4* __restrict__ xs,
                    const int* __restrict__ mask,
                    float4* __restrict__ out)
{
    // Select tensor for this block: 1 read stream + 1 write stream per block.
    const float4* __restrict__ src =
        (blockIdx.y == 0) ? xd : (blockIdx.y == 1) ? xt : xs;
    float4* __restrict__ dst = out + (long)blockIdx.y * N4_PER;

    long base = (long)blockIdx.x * F4_PER_BLOCK + threadIdx.x;

    const float4 z = make_float4(0.f, 0.f, 0.f, 0.f);
    float4 v[F4_PER_THREAD];
    bool  k[F4_PER_THREAD];
    long  idx[F4_PER_THREAD];

#pragma unroll
    for (int j = 0; j < F4_PER_THREAD; j++) {
        idx[j] = base + (long)j * BLK;               // warp-contiguous
        int t = (int)((idx[j] >> ROW_SHIFT) & T_MASK);
        k[j] = (mask[t] == 0);                       // 2 KB table, L1-resident
        v[j] = z;
    }

    // Front-batched independent predicated loads (up to 4 LDG.128 in flight).
#pragma unroll
    for (int j = 0; j < F4_PER_THREAD; j++) {
        if (k[j]) v[j] = __ldcs(&src[idx[j]]);
    }

#pragma unroll
    for (int j = 0; j < F4_PER_THREAD; j++) {
        __stcs(&dst[idx[j]], v[j]);
    }
}

extern "C" void kernel_launch(void* const* d_in, const int* in_sizes, int n_in,
                              void* d_out, int out_size)
{
    const float4* xd = (const float4*)d_in[0];
    const float4* xt = (const float4*)d_in[1];
    const float4* xs = (const float4*)d_in[2];
    const int* mask  = (const int*)d_in[3];
    float4* out = (float4*)d_out;

    dim3 grid((unsigned)(N4_PER / F4_PER_BLOCK), 3);  // (8192, 3), exact
    patch_masker_kernel<<<grid, BLK>>>(xd, xt, xs, mask, out);
}